// round 5
// baseline (speedup 1.0000x reference)
#include <cuda_runtime.h>

#define TT  1024
#define NUM 126
#define L   128
#define HB  128        // half batch: CTA handles batches (bid, bid+HB)

// monotone float -> uint key (order-preserving), and inverse
__device__ __forceinline__ unsigned fkey(float f) {
    int b = __float_as_int(f);
    return (unsigned)(b >= 0 ? (b ^ 0x80000000) : ~b);
}
__device__ __forceinline__ float finv(unsigned k) {
    int b = (k & 0x80000000u) ? (int)(k ^ 0x80000000u) : ~(int)k;
    return __int_as_float(b);
}

__global__ __launch_bounds__(128) void crf_fwd_kernel(
    const float* __restrict__ logits,     // [B, T, NUM]
    const int*   __restrict__ labels,     // [B, T]
    const int*   __restrict__ lens,       // [B]
    const float* __restrict__ trans,      // [L, L]
    float*       __restrict__ out)        // [B]
{
    const int b0   = blockIdx.x;
    const int b1   = blockIdx.x + HB;
    const int j    = threadIdx.x;        // one thread per state
    const int warp = j >> 5;
    const int lane = j & 31;
    const int la   = lens[b0];
    const int lb   = lens[b1];

    __shared__ __align__(16) float v[2][2][L];     // [parity][slot][state]
    __shared__ __align__(16) float wmax[2][2][4];  // [parity][slot][warp]
    __shared__ float sred[2][4];

    // ---- E2[i] = packed f32x2 { exp(trans[j][2i]), exp(trans[j][2i+1]) } ----
    unsigned long long E2[L / 2];
    #pragma unroll
    for (int i = 0; i < L / 2; ++i) {
        float lo = __expf(trans[j * L + 2 * i]);
        float hi = __expf(trans[j * L + 2 * i + 1]);
        asm("mov.b64 %0, {%1, %2};" : "=l"(E2[i]) : "f"(lo), "f"(hi));
    }

    // ---- gold scores (cooperative over time, both batches) ----
    const int*   labA = labels + b0 * TT;
    const int*   labB = labels + b1 * TT;
    const float* logA = logits + (size_t)b0 * TT * NUM;
    const float* logB = logits + (size_t)b1 * TT * NUM;

    float g0 = 0.f, g1 = 0.f;
    for (int t = j; t < la; t += L) {
        int lab = labA[t];
        g0 += logA[(size_t)t * NUM + lab];
        if (t > 0) g0 += trans[lab * L + labA[t - 1]];
    }
    for (int t = j; t < lb; t += L) {
        int lab = labB[t];
        g1 += logB[(size_t)t * NUM + lab];
        if (t > 0) g1 += trans[lab * L + labB[t - 1]];
    }
    if (j == 0) {
        g0 += trans[labA[0] * L + (L - 2)] + trans[(L - 1) * L + labA[la - 1]];
        g1 += trans[labB[0] * L + (L - 2)] + trans[(L - 1) * L + labB[lb - 1]];
    }
    #pragma unroll
    for (int o = 16; o; o >>= 1) {
        g0 += __shfl_xor_sync(0xffffffffu, g0, o);
        g1 += __shfl_xor_sync(0xffffffffu, g1, o);
    }
    if (lane == 0) { sred[0][warp] = g0; sred[1][warp] = g1; }
    __syncthreads();
    const float gold0 = sred[0][0] + sred[0][1] + sred[0][2] + sred[0][3];
    const float gold1 = sred[1][0] + sred[1][1] + sred[1][2] + sred[1][3];

    // ---- forward recursion state, per batch ----
    const float alpha0 = (j == L - 2) ? 0.f : -100.f;
    const float ev0    = __expf(alpha0);

    v[0][0][j] = ev0;   v[0][1][j] = ev0;
    if (j < 4) { wmax[0][0][j] = 0.f; wmax[0][1][j] = 0.f; }

    float sA = 1.f, baseA = alpha0, mA = 0.f, vA_last = ev0;
    float sB = 1.f, baseB = alpha0, mB = 0.f, vB_last = ev0;

    float lgA0 = (j < NUM) ? logA[j] : -1000.f;
    float lgA1 = (j < NUM && 1 < la) ? logA[NUM + j] : -1000.f;
    float lgB0 = (j < NUM) ? logB[j] : -1000.f;
    float lgB1 = (j < NUM && 1 < lb) ? logB[NUM + j] : -1000.f;

    const int tmax = (la > lb) ? la : lb;

    int p = 0;
    for (int t = 0; t < tmax; ++t) {
        __syncthreads();                             // ONE barrier / step

        // ================= batch A =================
        if (t < la) {
            float alpha_prev = baseA + __logf(sA);   // off critical path
            float mw = finv(__reduce_max_sync(0xffffffffu, fkey(alpha_prev)));
            if (lane == 0) wmax[p ^ 1][0][warp] = mw;

            float lg_n2 = -1000.f;
            if (j < NUM && t + 2 < la)
                lg_n2 = logA[(size_t)(t + 2) * NUM + j];

            float4 w4 = *(const float4*)wmax[p][0];
            float m_cur = fmaxf(fmaxf(w4.x, w4.y), fmaxf(w4.z, w4.w));
            float u = __expf(lgA0 + mA - m_cur);

            const ulonglong2* v2 = (const ulonglong2*)v[p][0];
            unsigned long long a0 = 0ull, a1 = 0ull, a2 = 0ull, a3 = 0ull;
            #pragma unroll
            for (int i = 0; i < 16; ++i) {
                ulonglong2 x = v2[2 * i];
                ulonglong2 y = v2[2 * i + 1];
                asm("fma.rn.f32x2 %0, %1, %2, %0;" : "+l"(a0) : "l"(E2[4*i    ]), "l"(x.x));
                asm("fma.rn.f32x2 %0, %1, %2, %0;" : "+l"(a1) : "l"(E2[4*i + 1]), "l"(x.y));
                asm("fma.rn.f32x2 %0, %1, %2, %0;" : "+l"(a2) : "l"(E2[4*i + 2]), "l"(y.x));
                asm("fma.rn.f32x2 %0, %1, %2, %0;" : "+l"(a3) : "l"(E2[4*i + 3]), "l"(y.y));
            }
            unsigned long long s01, s23, sall;
            asm("add.rn.f32x2 %0, %1, %2;" : "=l"(s01)  : "l"(a0),  "l"(a1));
            asm("add.rn.f32x2 %0, %1, %2;" : "=l"(s23)  : "l"(a2),  "l"(a3));
            asm("add.rn.f32x2 %0, %1, %2;" : "=l"(sall) : "l"(s01), "l"(s23));
            float plo, phi;
            asm("mov.b64 {%0, %1}, %2;" : "=f"(plo), "=f"(phi) : "l"(sall));
            float s = plo + phi;

            vA_last = s * u;
            v[p ^ 1][0][j] = vA_last;

            baseA = lgA0 + mA;  sA = s;  mA = m_cur;
            lgA0 = lgA1;  lgA1 = lg_n2;
        } else {
            v[p ^ 1][0][j] = vA_last;                // frozen: alpha unchanged
        }

        // ================= batch B =================
        if (t < lb) {
            float alpha_prev = baseB + __logf(sB);
            float mw = finv(__reduce_max_sync(0xffffffffu, fkey(alpha_prev)));
            if (lane == 0) wmax[p ^ 1][1][warp] = mw;

            float lg_n2 = -1000.f;
            if (j < NUM && t + 2 < lb)
                lg_n2 = logB[(size_t)(t + 2) * NUM + j];

            float4 w4 = *(const float4*)wmax[p][1];
            float m_cur = fmaxf(fmaxf(w4.x, w4.y), fmaxf(w4.z, w4.w));
            float u = __expf(lgB0 + mB - m_cur);

            const ulonglong2* v2 = (const ulonglong2*)v[p][1];
            unsigned long long a0 = 0ull, a1 = 0ull, a2 = 0ull, a3 = 0ull;
            #pragma unroll
            for (int i = 0; i < 16; ++i) {
                ulonglong2 x = v2[2 * i];
                ulonglong2 y = v2[2 * i + 1];
                asm("fma.rn.f32x2 %0, %1, %2, %0;" : "+l"(a0) : "l"(E2[4*i    ]), "l"(x.x));
                asm("fma.rn.f32x2 %0, %1, %2, %0;" : "+l"(a1) : "l"(E2[4*i + 1]), "l"(x.y));
                asm("fma.rn.f32x2 %0, %1, %2, %0;" : "+l"(a2) : "l"(E2[4*i + 2]), "l"(y.x));
                asm("fma.rn.f32x2 %0, %1, %2, %0;" : "+l"(a3) : "l"(E2[4*i + 3]), "l"(y.y));
            }
            unsigned long long s01, s23, sall;
            asm("add.rn.f32x2 %0, %1, %2;" : "=l"(s01)  : "l"(a0),  "l"(a1));
            asm("add.rn.f32x2 %0, %1, %2;" : "=l"(s23)  : "l"(a2),  "l"(a3));
            asm("add.rn.f32x2 %0, %1, %2;" : "=l"(sall) : "l"(s01), "l"(s23));
            float plo, phi;
            asm("mov.b64 {%0, %1}, %2;" : "=f"(plo), "=f"(phi) : "l"(sall));
            float s = plo + phi;

            vB_last = s * u;
            v[p ^ 1][1][j] = vB_last;

            baseB = lgB0 + mB;  sB = s;  mB = m_cur;
            lgB0 = lgB1;  lgB1 = lg_n2;
        } else {
            v[p ^ 1][1][j] = vB_last;
        }

        p ^= 1;
    }

    // ---- finalize both batches: exact logsumexp ----
    __syncthreads();
    const float tend = trans[(L - 1) * L + j];
    float alA = baseA + __logf(sA) + tend;
    float alB = baseB + __logf(sB) + tend;

    float mwA = finv(__reduce_max_sync(0xffffffffu, fkey(alA)));
    float mwB = finv(__reduce_max_sync(0xffffffffu, fkey(alB)));
    if (lane == 0) { wmax[0][0][warp] = mwA; wmax[0][1][warp] = mwB; }
    __syncthreads();
    float4 wa = *(const float4*)wmax[0][0];
    float4 wb = *(const float4*)wmax[0][1];
    const float mgA = fmaxf(fmaxf(wa.x, wa.y), fmaxf(wa.z, wa.w));
    const float mgB = fmaxf(fmaxf(wb.x, wb.y), fmaxf(wb.z, wb.w));

    float eA = __expf(alA - mgA);
    float eB = __expf(alB - mgB);
    #pragma unroll
    for (int o = 16; o; o >>= 1) {
        eA += __shfl_xor_sync(0xffffffffu, eA, o);
        eB += __shfl_xor_sync(0xffffffffu, eB, o);
    }
    if (lane == 0) { sred[0][warp] = eA; sred[1][warp] = eB; }
    __syncthreads();

    if (j == 0) {
        float SA = sred[0][0] + sred[0][1] + sred[0][2] + sred[0][3];
        float SB = sred[1][0] + sred[1][1] + sred[1][2] + sred[1][3];
        out[b0] = gold0 - (mgA + __logf(SA));
        out[b1] = gold1 - (mgB + __logf(SB));
    }
}

extern "C" void kernel_launch(void* const* d_in, const int* in_sizes, int n_in,
                              void* d_out, int out_size)
{
    const float* logits = (const float*)d_in[0];
    const int*   labels = (const int*)  d_in[1];
    const int*   lens   = (const int*)  d_in[2];
    const float* trans  = (const float*)d_in[3];
    float*       out    = (float*)d_out;

    crf_fwd_kernel<<<HB, L>>>(logits, labels, lens, trans, out);
}

// round 7
// speedup vs baseline: 3.1233x; 3.1233x over previous
#include <cuda_runtime.h>

#define TT  1024
#define NUM 126
#define L   128
#define B_  256

__device__ int d_perm[B_];   // batch indices sorted by len ascending

// monotone float -> uint key (order-preserving), and inverse
__device__ __forceinline__ unsigned fkey(float f) {
    int b = __float_as_int(f);
    return (unsigned)(b >= 0 ? (b ^ 0x80000000) : ~b);
}
__device__ __forceinline__ float finv(unsigned k) {
    int b = (k & 0x80000000u) ? (int)(k ^ 0x80000000u) : ~(int)k;
    return __int_as_float(b);
}

// ---- tiny prelude: bitonic sort 256 (len, idx) keys, ascending ----
__global__ void sort_lens_kernel(const int* __restrict__ lens) {
    __shared__ unsigned key[B_];
    const int t = threadIdx.x;
    key[t] = ((unsigned)lens[t] << 8) | (unsigned)t;   // len<=1024 fits; idx tiebreak
    __syncthreads();
    for (int k = 2; k <= B_; k <<= 1) {
        for (int s = k >> 1; s > 0; s >>= 1) {
            int ixj = t ^ s;
            if (ixj > t) {
                unsigned a = key[t], c = key[ixj];
                bool asc = ((t & k) == 0);
                if (asc ? (a > c) : (a < c)) { key[t] = c; key[ixj] = a; }
            }
            __syncthreads();
        }
    }
    d_perm[t] = (int)(key[t] & 0xffu);
}

__global__ __launch_bounds__(128, 1) void crf_fwd_kernel(
    const float* __restrict__ logits,     // [B, T, NUM]
    const int*   __restrict__ labels,     // [B, T]
    const int*   __restrict__ lens,       // [B]
    const float* __restrict__ trans,      // [L, L]
    float*       __restrict__ out)        // [B]
{
    const int b0 = d_perm[B_ - 1 - blockIdx.x];   // long sequence
    const int b1 = d_perm[blockIdx.x];            // short sequence
    const int j    = threadIdx.x;
    const int warp = j >> 5;
    const int lane = j & 31;
    const int la   = lens[b0];
    const int lb   = lens[b1];

    __shared__ __align__(16) float v[2][2][L];     // [parity][slot][state]
    __shared__ __align__(16) float wmax[2][2][4];  // [parity][slot][warp]
    __shared__ float sred[2][4];

    // ---- E2[i] = packed f32x2 { exp(trans[j][2i]), exp(trans[j][2i+1]) } ----
    unsigned long long E2[L / 2];
    #pragma unroll
    for (int i = 0; i < L / 2; ++i) {
        float lo = __expf(trans[j * L + 2 * i]);
        float hi = __expf(trans[j * L + 2 * i + 1]);
        asm("mov.b64 %0, {%1, %2};" : "=l"(E2[i]) : "f"(lo), "f"(hi));
    }

    // ---- gold scores (cooperative over time, both batches) ----
    const int*   labA = labels + b0 * TT;
    const int*   labB = labels + b1 * TT;
    const float* logA = logits + (size_t)b0 * TT * NUM;
    const float* logB = logits + (size_t)b1 * TT * NUM;

    float g0 = 0.f, g1 = 0.f;
    for (int t = j; t < la; t += L) {
        int lab = labA[t];
        g0 += logA[(size_t)t * NUM + lab];
        if (t > 0) g0 += trans[lab * L + labA[t - 1]];
    }
    for (int t = j; t < lb; t += L) {
        int lab = labB[t];
        g1 += logB[(size_t)t * NUM + lab];
        if (t > 0) g1 += trans[lab * L + labB[t - 1]];
    }
    if (j == 0) {
        g0 += trans[labA[0] * L + (L - 2)] + trans[(L - 1) * L + labA[la - 1]];
        g1 += trans[labB[0] * L + (L - 2)] + trans[(L - 1) * L + labB[lb - 1]];
    }
    #pragma unroll
    for (int o = 16; o; o >>= 1) {
        g0 += __shfl_xor_sync(0xffffffffu, g0, o);
        g1 += __shfl_xor_sync(0xffffffffu, g1, o);
    }
    if (lane == 0) { sred[0][warp] = g0; sred[1][warp] = g1; }
    __syncthreads();
    const float gold0 = sred[0][0] + sred[0][1] + sred[0][2] + sred[0][3];
    const float gold1 = sred[1][0] + sred[1][1] + sred[1][2] + sred[1][3];

    // ---- forward recursion state, per batch ----
    const float alpha0 = (j == L - 2) ? 0.f : -100.f;
    const float ev0    = __expf(alpha0);

    v[0][0][j] = ev0;   v[0][1][j] = ev0;
    if (j < 4) { wmax[0][0][j] = 0.f; wmax[0][1][j] = 0.f; }

    float sA = 1.f, baseA = alpha0, mA = 0.f;
    float sB = 1.f, baseB = alpha0, mB = 0.f;

    // logit pipeline, depth 3 (lead >= 577cyc DRAM latency)
    float lgA0 = (j < NUM) ? logA[j] : -1000.f;
    float lgA1 = (j < NUM && 1 < la) ? logA[(size_t)1 * NUM + j] : -1000.f;
    float lgA2 = (j < NUM && 2 < la) ? logA[(size_t)2 * NUM + j] : -1000.f;
    float lgB0 = (j < NUM) ? logB[j] : -1000.f;
    float lgB1 = (j < NUM && 1 < lb) ? logB[(size_t)1 * NUM + j] : -1000.f;
    float lgB2 = (j < NUM && 2 < lb) ? logB[(size_t)2 * NUM + j] : -1000.f;

    const int tmax = (la > lb) ? la : lb;

    int p = 0;
    for (int t = 0; t < tmax; ++t) {
        __syncthreads();                             // ONE barrier / step

        // ================= batch A (long) =================
        if (t < la) {
            float alpha_prev = baseA + __logf(sA);   // off critical path
            float mw = finv(__reduce_max_sync(0xffffffffu, fkey(alpha_prev)));
            if (lane == 0) wmax[p ^ 1][0][warp] = mw;

            float lg_n3 = -1000.f;
            if (j < NUM && t + 3 < la)
                lg_n3 = logA[(size_t)(t + 3) * NUM + j];

            float4 w4 = *(const float4*)wmax[p][0];
            float m_cur = fmaxf(fmaxf(w4.x, w4.y), fmaxf(w4.z, w4.w));
            float u = __expf(lgA0 + mA - m_cur);

            const ulonglong2* v2 = (const ulonglong2*)v[p][0];
            unsigned long long a0 = 0ull, a1 = 0ull, a2 = 0ull, a3 = 0ull;
            #pragma unroll
            for (int i = 0; i < 16; ++i) {
                ulonglong2 x = v2[2 * i];
                ulonglong2 y = v2[2 * i + 1];
                asm("fma.rn.f32x2 %0, %1, %2, %0;" : "+l"(a0) : "l"(E2[4*i    ]), "l"(x.x));
                asm("fma.rn.f32x2 %0, %1, %2, %0;" : "+l"(a1) : "l"(E2[4*i + 1]), "l"(x.y));
                asm("fma.rn.f32x2 %0, %1, %2, %0;" : "+l"(a2) : "l"(E2[4*i + 2]), "l"(y.x));
                asm("fma.rn.f32x2 %0, %1, %2, %0;" : "+l"(a3) : "l"(E2[4*i + 3]), "l"(y.y));
            }
            unsigned long long s01, s23, sall;
            asm("add.rn.f32x2 %0, %1, %2;" : "=l"(s01)  : "l"(a0),  "l"(a1));
            asm("add.rn.f32x2 %0, %1, %2;" : "=l"(s23)  : "l"(a2),  "l"(a3));
            asm("add.rn.f32x2 %0, %1, %2;" : "=l"(sall) : "l"(s01), "l"(s23));
            float plo, phi;
            asm("mov.b64 {%0, %1}, %2;" : "=f"(plo), "=f"(phi) : "l"(sall));
            float s = plo + phi;

            v[p ^ 1][0][j] = s * u;

            baseA = lgA0 + mA;  sA = s;  mA = m_cur;
            lgA0 = lgA1;  lgA1 = lgA2;  lgA2 = lg_n3;
        }

        // ================= batch B (short) =================
        if (t < lb) {
            float alpha_prev = baseB + __logf(sB);
            float mw = finv(__reduce_max_sync(0xffffffffu, fkey(alpha_prev)));
            if (lane == 0) wmax[p ^ 1][1][warp] = mw;

            float lg_n3 = -1000.f;
            if (j < NUM && t + 3 < lb)
                lg_n3 = logB[(size_t)(t + 3) * NUM + j];

            float4 w4 = *(const float4*)wmax[p][1];
            float m_cur = fmaxf(fmaxf(w4.x, w4.y), fmaxf(w4.z, w4.w));
            float u = __expf(lgB0 + mB - m_cur);

            const ulonglong2* v2 = (const ulonglong2*)v[p][1];
            unsigned long long a0 = 0ull, a1 = 0ull, a2 = 0ull, a3 = 0ull;
            #pragma unroll
            for (int i = 0; i < 16; ++i) {
                ulonglong2 x = v2[2 * i];
                ulonglong2 y = v2[2 * i + 1];
                asm("fma.rn.f32x2 %0, %1, %2, %0;" : "+l"(a0) : "l"(E2[4*i    ]), "l"(x.x));
                asm("fma.rn.f32x2 %0, %1, %2, %0;" : "+l"(a1) : "l"(E2[4*i + 1]), "l"(x.y));
                asm("fma.rn.f32x2 %0, %1, %2, %0;" : "+l"(a2) : "l"(E2[4*i + 2]), "l"(y.x));
                asm("fma.rn.f32x2 %0, %1, %2, %0;" : "+l"(a3) : "l"(E2[4*i + 3]), "l"(y.y));
            }
            unsigned long long s01, s23, sall;
            asm("add.rn.f32x2 %0, %1, %2;" : "=l"(s01)  : "l"(a0),  "l"(a1));
            asm("add.rn.f32x2 %0, %1, %2;" : "=l"(s23)  : "l"(a2),  "l"(a3));
            asm("add.rn.f32x2 %0, %1, %2;" : "=l"(sall) : "l"(s01), "l"(s23));
            float plo, phi;
            asm("mov.b64 {%0, %1}, %2;" : "=f"(plo), "=f"(phi) : "l"(sall));
            float s = plo + phi;

            v[p ^ 1][1][j] = s * u;

            baseB = lgB0 + mB;  sB = s;  mB = m_cur;
            lgB0 = lgB1;  lgB1 = lgB2;  lgB2 = lg_n3;
        }

        p ^= 1;
    }

    // ---- finalize both batches: exact logsumexp ----
    __syncthreads();
    const float tend = trans[(L - 1) * L + j];
    float alA = baseA + __logf(sA) + tend;
    float alB = baseB + __logf(sB) + tend;

    float mwA = finv(__reduce_max_sync(0xffffffffu, fkey(alA)));
    float mwB = finv(__reduce_max_sync(0xffffffffu, fkey(alB)));
    if (lane == 0) { wmax[0][0][warp] = mwA; wmax[0][1][warp] = mwB; }
    __syncthreads();
    float4 wa = *(const float4*)wmax[0][0];
    float4 wb = *(const float4*)wmax[0][1];
    const float mgA = fmaxf(fmaxf(wa.x, wa.y), fmaxf(wa.z, wa.w));
    const float mgB = fmaxf(fmaxf(wb.x, wb.y), fmaxf(wb.z, wb.w));

    float eA = __expf(alA - mgA);
    float eB = __expf(alB - mgB);
    #pragma unroll
    for (int o = 16; o; o >>= 1) {
        eA += __shfl_xor_sync(0xffffffffu, eA, o);
        eB += __shfl_xor_sync(0xffffffffu, eB, o);
    }
    if (lane == 0) { sred[0][warp] = eA; sred[1][warp] = eB; }
    __syncthreads();

    if (j == 0) {
        float SA = sred[0][0] + sred[0][1] + sred[0][2] + sred[0][3];
        float SB = sred[1][0] + sred[1][1] + sred[1][2] + sred[1][3];
        out[b0] = gold0 - (mgA + __logf(SA));
        out[b1] = gold1 - (mgB + __logf(SB));
    }
}

extern "C" void kernel_launch(void* const* d_in, const int* in_sizes, int n_in,
                              void* d_out, int out_size)
{
    const float* logits = (const float*)d_in[0];
    const int*   labels = (const int*)  d_in[1];
    const int*   lens   = (const int*)  d_in[2];
    const float* trans  = (const float*)d_in[3];
    float*       out    = (float*)d_out;

    sort_lens_kernel<<<1, B_>>>(lens);
    crf_fwd_kernel<<<B_ / 2, L>>>(logits, labels, lens, trans, out);
}

// round 8
// speedup vs baseline: 3.3841x; 1.0835x over previous
#include <cuda_runtime.h>

#define TT  1024
#define NUM 126
#define L   128
#define B_  256

__device__ int d_perm[B_];   // batch indices sorted by len ascending

// monotone float -> uint key (order-preserving), and inverse
__device__ __forceinline__ unsigned fkey(float f) {
    int b = __float_as_int(f);
    return (unsigned)(b >= 0 ? (b ^ 0x80000000) : ~b);
}
__device__ __forceinline__ float finv(unsigned k) {
    int b = (k & 0x80000000u) ? (int)(k ^ 0x80000000u) : ~(int)k;
    return __int_as_float(b);
}

// ---- tiny prelude: bitonic sort 256 (len, idx) keys, ascending ----
__global__ void sort_lens_kernel(const int* __restrict__ lens) {
    __shared__ unsigned key[B_];
    const int t = threadIdx.x;
    key[t] = ((unsigned)lens[t] << 8) | (unsigned)t;
    __syncthreads();
    for (int k = 2; k <= B_; k <<= 1) {
        for (int s = k >> 1; s > 0; s >>= 1) {
            int ixj = t ^ s;
            if (ixj > t) {
                unsigned a = key[t], c = key[ixj];
                bool asc = ((t & k) == 0);
                if (asc ? (a > c) : (a < c)) { key[t] = c; key[ixj] = a; }
            }
            __syncthreads();
        }
    }
    d_perm[t] = (int)(key[t] & 0xffu);
}

__global__ __launch_bounds__(256, 1) void crf_fwd_kernel(
    const float* __restrict__ logits,     // [B, T, NUM]
    const int*   __restrict__ labels,     // [B, T]
    const int*   __restrict__ lens,       // [B]
    const float* __restrict__ trans,      // [L, L]
    float*       __restrict__ out)        // [B]
{
    const int tid  = threadIdx.x;
    const int grp  = tid >> 7;            // 0 = long seq, 1 = short seq
    const int j    = tid & (L - 1);       // state index within group
    const int gw   = j >> 5;              // warp index within group (0..3)
    const int lane = tid & 31;

    // group 0 <- long sequence, group 1 <- short sequence (sorted anti-pair)
    const int myb  = grp ? d_perm[blockIdx.x] : d_perm[B_ - 1 - blockIdx.x];
    const int len  = lens[myb];

    __shared__ __align__(16) float v[2][2][L];     // [parity][group][state]
    __shared__ __align__(16) float wmax[2][2][4];  // [parity][group][warp]
    __shared__ float sred[2][4];

    // ---- E2[i] = packed f32x2 { exp(trans[j][2i]), exp(trans[j][2i+1]) } ----
    unsigned long long E2[L / 2];
    #pragma unroll
    for (int i = 0; i < L / 2; ++i) {
        float lo = __expf(trans[j * L + 2 * i]);
        float hi = __expf(trans[j * L + 2 * i + 1]);
        asm("mov.b64 %0, {%1, %2};" : "=l"(E2[i]) : "f"(lo), "f"(hi));
    }

    // ---- gold score (each group covers its own sequence) ----
    const int*   lab_b = labels + myb * TT;
    const float* log_b = logits + (size_t)myb * TT * NUM;

    float g = 0.f;
    for (int t = j; t < len; t += L) {
        int lab = lab_b[t];
        g += log_b[(size_t)t * NUM + lab];
        if (t > 0) g += trans[lab * L + lab_b[t - 1]];
    }
    if (j == 0) {
        g += trans[lab_b[0] * L + (L - 2)] + trans[(L - 1) * L + lab_b[len - 1]];
    }
    #pragma unroll
    for (int o = 16; o; o >>= 1) g += __shfl_xor_sync(0xffffffffu, g, o);
    if (lane == 0) sred[grp][gw] = g;
    __syncthreads();
    const float gold = sred[grp][0] + sred[grp][1] + sred[grp][2] + sred[grp][3];

    // ---- forward recursion state ----
    const float alpha0 = (j == L - 2) ? 0.f : -100.f;

    v[0][grp][j] = __expf(alpha0);
    if (j < 4) wmax[0][grp][j] = 0.f;

    float s_prev = 1.f, base_prev = alpha0, m_used = 0.f;

    // logit pipeline, depth 3 (lead >= 577cyc DRAM latency)
    float lg0 = (j < NUM) ? log_b[j] : -1000.f;
    float lg1 = (j < NUM && 1 < len) ? log_b[(size_t)1 * NUM + j] : -1000.f;
    float lg2 = (j < NUM && 2 < len) ? log_b[(size_t)2 * NUM + j] : -1000.f;

    // all threads in the block agree on tmax (group 0 holds the long one)
    const int la = lens[d_perm[B_ - 1 - blockIdx.x]];
    const int lb = lens[d_perm[blockIdx.x]];
    const int tmax = (la > lb) ? la : lb;

    int p = 0;
    for (int t = 0; t < tmax; ++t) {
        __syncthreads();                             // ONE barrier / step

        if (t < len) {
            // off-critical-path: previous alpha -> lagged per-warp max
            float alpha_prev = base_prev + __logf(s_prev);
            float mw = finv(__reduce_max_sync(0xffffffffu, fkey(alpha_prev)));
            if (lane == 0) wmax[p ^ 1][grp][gw] = mw;

            float lg_n3 = -1000.f;
            if (j < NUM && t + 3 < len)
                lg_n3 = log_b[(size_t)(t + 3) * NUM + j];

            // shift for this step (lag-2 max), u-factor (off dot path)
            float4 w4 = *(const float4*)wmax[p][grp];
            float m_cur = fmaxf(fmaxf(w4.x, w4.y), fmaxf(w4.z, w4.w));
            float u = __expf(lg0 + m_used - m_cur);

            // critical path: s = dot(E[j][:], v_{t-1})
            const ulonglong2* v2 = (const ulonglong2*)v[p][grp];
            unsigned long long a0 = 0ull, a1 = 0ull, a2 = 0ull, a3 = 0ull;
            #pragma unroll
            for (int i = 0; i < 16; ++i) {
                ulonglong2 x = v2[2 * i];
                ulonglong2 y = v2[2 * i + 1];
                asm("fma.rn.f32x2 %0, %1, %2, %0;" : "+l"(a0) : "l"(E2[4*i    ]), "l"(x.x));
                asm("fma.rn.f32x2 %0, %1, %2, %0;" : "+l"(a1) : "l"(E2[4*i + 1]), "l"(x.y));
                asm("fma.rn.f32x2 %0, %1, %2, %0;" : "+l"(a2) : "l"(E2[4*i + 2]), "l"(y.x));
                asm("fma.rn.f32x2 %0, %1, %2, %0;" : "+l"(a3) : "l"(E2[4*i + 3]), "l"(y.y));
            }
            unsigned long long s01, s23, sall;
            asm("add.rn.f32x2 %0, %1, %2;" : "=l"(s01)  : "l"(a0),  "l"(a1));
            asm("add.rn.f32x2 %0, %1, %2;" : "=l"(s23)  : "l"(a2),  "l"(a3));
            asm("add.rn.f32x2 %0, %1, %2;" : "=l"(sall) : "l"(s01), "l"(s23));
            float plo, phi;
            asm("mov.b64 {%0, %1}, %2;" : "=f"(plo), "=f"(phi) : "l"(sall));
            float s = plo + phi;

            v[p ^ 1][grp][j] = s * u;                // no exp/log on this path

            base_prev = lg0 + m_used;
            s_prev = s;  m_used = m_cur;
            lg0 = lg1;  lg1 = lg2;  lg2 = lg_n3;
        }

        p ^= 1;
    }

    // ---- finalize: exact logsumexp per group ----
    __syncthreads();
    float alpha = base_prev + __logf(s_prev) + trans[(L - 1) * L + j];

    float mw = finv(__reduce_max_sync(0xffffffffu, fkey(alpha)));
    if (lane == 0) wmax[0][grp][gw] = mw;
    __syncthreads();
    float4 w4 = *(const float4*)wmax[0][grp];
    const float mg = fmaxf(fmaxf(w4.x, w4.y), fmaxf(w4.z, w4.w));

    float e = __expf(alpha - mg);
    #pragma unroll
    for (int o = 16; o; o >>= 1) e += __shfl_xor_sync(0xffffffffu, e, o);
    if (lane == 0) sred[grp][gw] = e;
    __syncthreads();

    if (j == 0) {
        float S = sred[grp][0] + sred[grp][1] + sred[grp][2] + sred[grp][3];
        out[myb] = gold - (mg + __logf(S));
    }
}

extern "C" void kernel_launch(void* const* d_in, const int* in_sizes, int n_in,
                              void* d_out, int out_size)
{
    const float* logits = (const float*)d_in[0];
    const int*   labels = (const int*)  d_in[1];
    const int*   lens   = (const int*)  d_in[2];
    const float* trans  = (const float*)d_in[3];
    float*       out    = (float*)d_out;

    sort_lens_kernel<<<1, B_>>>(lens);
    crf_fwd_kernel<<<B_ / 2, 256>>>(logits, labels, lens, trans, out);
}